// round 2
// baseline (speedup 1.0000x reference)
#include <cuda_runtime.h>

// HybridLoss: smooth_l1(preds,targets) + 0.5*(1 - mean(box_overlap))
// preds, targets: [2000000, 10] float32 row-major. Output: 1 float scalar.
// Single fused kernel: block partial sums -> global atomics -> last block
// finalizes output and self-resets state (graph-replay safe).

#define NROWS 2000000
#define THREADS 256
#define ROWS_PER_THREAD 2
#define ROWS_PER_BLOCK (THREADS * ROWS_PER_THREAD)              // 512
#define NBLOCKS ((NROWS + ROWS_PER_BLOCK - 1) / ROWS_PER_BLOCK) // 3907
#define EPSF 1e-6f

__device__ double g_acc[2] = {0.0, 0.0};  // [0]=smooth-l1 sum, [1]=overlap sum
__device__ unsigned int g_ticket = 0;

// ---- per-row math: returns (l1_sum, overlap) accumulated into refs ----
__device__ __forceinline__ void row_math(const float* __restrict__ p,
                                         const float* __restrict__ t,
                                         float& l1_acc, float& ov_acc)
{
    // smooth L1
    #pragma unroll
    for (int j = 0; j < 10; j++) {
        float d  = p[j] - t[j];
        float ad = fabsf(d);
        l1_acc += (ad < 1.0f) ? 0.5f * d * d : ad - 0.5f;
    }

    // quaternions -> rotation matrices
    float px = p[6], py = p[7], pz = p[8], pw = p[9];
    float gx = t[6], gy = t[7], gz = t[8], gw = t[9];
    float pin = rsqrtf(px*px + py*py + pz*pz + pw*pw);
    float gin = rsqrtf(gx*gx + gy*gy + gz*gz + gw*gw);
    px *= pin; py *= pin; pz *= pin; pw *= pin;
    gx *= gin; gy *= gin; gz *= gin; gw *= gin;

    float pr[9], gr[9];
    pr[0] = 1.0f - 2.0f*(py*py + pz*pz);
    pr[1] = 2.0f*(px*py + pz*pw);
    pr[2] = 2.0f*(px*pz - py*pw);
    pr[3] = 2.0f*(px*py - pz*pw);
    pr[4] = 1.0f - 2.0f*(px*px + pz*pz);
    pr[5] = 2.0f*(py*pz + px*pw);
    pr[6] = 2.0f*(px*pz + py*pw);
    pr[7] = 2.0f*(py*pz - px*pw);
    pr[8] = 1.0f - 2.0f*(px*px + py*py);

    gr[0] = 1.0f - 2.0f*(gy*gy + gz*gz);
    gr[1] = 2.0f*(gx*gy + gz*gw);
    gr[2] = 2.0f*(gx*gz - gy*gw);
    gr[3] = 2.0f*(gx*gy - gz*gw);
    gr[4] = 1.0f - 2.0f*(gx*gx + gz*gz);
    gr[5] = 2.0f*(gy*gz + gx*gw);
    gr[6] = 2.0f*(gx*gz + gy*gw);
    gr[7] = 2.0f*(gy*gz - gx*gw);
    gr[8] = 1.0f - 2.0f*(gx*gx + gy*gy);

    float dot = 0.0f;
    #pragma unroll
    for (int j = 0; j < 9; j++) dot += pr[j] * gr[j];
    float rot_align = fminf(fmaxf(dot * (1.0f / 3.0f), 0.0f), 1.0f);

    float prod = 1.0f;
    #pragma unroll
    for (int i = 0; i < 3; i++) {
        float pe = 0.5f * fabsf(pr[3*i]*p[3] + pr[3*i+1]*p[4] + pr[3*i+2]*p[5]);
        float ge = 0.5f * fabsf(gr[3*i]*t[3] + gr[3*i+1]*t[4] + gr[3*i+2]*t[5]);
        float cd  = fabsf(p[i] - t[i]);
        float num = fmaxf(2.0f * fminf(pe, ge) - cd, 0.0f);
        prod *= num / (pe + ge + EPSF);
    }
    ov_acc += fminf(fmaxf(prod * rot_align, 0.0f), 1.0f);
}

__global__ __launch_bounds__(THREADS) void hl_fused_kernel(
    const float* __restrict__ preds,
    const float* __restrict__ targets,
    float* __restrict__ out)
{
    __shared__ float sp[ROWS_PER_BLOCK * 10];
    __shared__ float st[ROWS_PER_BLOCK * 10];

    const int tid  = threadIdx.x;
    const int base = blockIdx.x * ROWS_PER_BLOCK;

    // ---- Stage rows via coalesced float4 loads (base*40 B is 16B-aligned) ----
    const long base4  = (long)base * 10 / 4;          // float4 offset into input
    const long total4 = (long)NROWS * 10 / 4;         // 5,000,000
    const float4* __restrict__ p4 = reinterpret_cast<const float4*>(preds)   + base4;
    const float4* __restrict__ t4 = reinterpret_cast<const float4*>(targets) + base4;
    float4* sp4 = reinterpret_cast<float4*>(sp);
    float4* st4 = reinterpret_cast<float4*>(st);

    #pragma unroll
    for (int k = 0; k < 5; k++) {                     // 1280 float4 per array
        int i4 = tid + k * THREADS;
        if ((base4 + i4) < total4) {
            sp4[i4] = p4[i4];
            st4[i4] = t4[i4];
        }
    }
    __syncthreads();

    float l1_sum = 0.0f;
    float ov     = 0.0f;

    #pragma unroll
    for (int r = 0; r < ROWS_PER_THREAD; r++) {
        const int lrow = tid + r * THREADS;           // row within block
        const int grow = base + lrow;
        if (grow < NROWS) {
            // rows are 40B-aligned in smem -> float2 loads
            float p[10], t[10];
            const float2* __restrict__ rp = reinterpret_cast<const float2*>(sp + lrow * 10);
            const float2* __restrict__ rt = reinterpret_cast<const float2*>(st + lrow * 10);
            #pragma unroll
            for (int j = 0; j < 5; j++) {
                float2 a = rp[j];  p[2*j] = a.x;  p[2*j+1] = a.y;
                float2 b = rt[j];  t[2*j] = b.x;  t[2*j+1] = b.y;
            }
            row_math(p, t, l1_sum, ov);
        }
    }

    // ---- block reduction ----
    #pragma unroll
    for (int off = 16; off > 0; off >>= 1) {
        l1_sum += __shfl_down_sync(0xFFFFFFFFu, l1_sum, off);
        ov     += __shfl_down_sync(0xFFFFFFFFu, ov, off);
    }
    __shared__ float warp_l1[THREADS / 32];
    __shared__ float warp_ov[THREADS / 32];
    const int lane = tid & 31;
    const int wid  = tid >> 5;
    if (lane == 0) { warp_l1[wid] = l1_sum; warp_ov[wid] = ov; }
    __syncthreads();

    if (wid == 0) {
        float a = (lane < THREADS / 32) ? warp_l1[lane] : 0.0f;
        float b = (lane < THREADS / 32) ? warp_ov[lane] : 0.0f;
        #pragma unroll
        for (int off = 4; off > 0; off >>= 1) {
            a += __shfl_down_sync(0xFFFFFFFFu, a, off);
            b += __shfl_down_sync(0xFFFFFFFFu, b, off);
        }
        if (lane == 0) {
            atomicAdd(&g_acc[0], (double)a);
            atomicAdd(&g_acc[1], (double)b);
            __threadfence();
            unsigned int ticket = atomicAdd(&g_ticket, 1u);
            if (ticket == (unsigned int)(NBLOCKS - 1)) {
                // all blocks' atomics are visible (fence-before-ticket on each)
                double s0 = *((volatile double*)&g_acc[0]);
                double s1 = *((volatile double*)&g_acc[1]);
                double param_loss = s0 / ((double)NROWS * 10.0);
                double mean_ov    = s1 / (double)NROWS;
                out[0] = (float)(param_loss + 0.5 * (1.0 - mean_ov));
                // self-reset for next graph replay
                *((volatile double*)&g_acc[0]) = 0.0;
                *((volatile double*)&g_acc[1]) = 0.0;
                __threadfence();
                g_ticket = 0;
                __threadfence();
            }
        }
    }
}

extern "C" void kernel_launch(void* const* d_in, const int* in_sizes, int n_in,
                              void* d_out, int out_size) {
    const float* preds   = (const float*)d_in[0];
    const float* targets = (const float*)d_in[1];
    float* out = (float*)d_out;

    hl_fused_kernel<<<NBLOCKS, THREADS>>>(preds, targets, out);
}

// round 3
// speedup vs baseline: 1.0377x; 1.0377x over previous
#include <cuda_runtime.h>

// HybridLoss: smooth_l1(preds,targets) + 0.5*(1 - mean(box_overlap))
// preds, targets: [2000000, 10] float32 row-major. Output: 1 float scalar.
//
// 2 rows per thread = 80 contiguous aligned bytes -> 5x LDG.128 per array,
// no shared-memory staging at all. Single fused kernel; last block finalizes
// and self-resets (graph-replay safe).

#define NROWS 2000000
#define THREADS 256
#define PAIRS (NROWS / 2)                                   // 1,000,000 threads
#define NBLOCKS ((PAIRS + THREADS - 1) / THREADS)           // 3907
#define EPSF 1e-6f

__device__ double g_acc[2] = {0.0, 0.0};  // [0]=smooth-l1 sum, [1]=overlap sum
__device__ unsigned int g_ticket = 0;

__device__ __forceinline__ void row_math(const float* __restrict__ p,
                                         const float* __restrict__ t,
                                         float& l1_acc, float& ov_acc)
{
    // smooth L1
    #pragma unroll
    for (int j = 0; j < 10; j++) {
        float d  = p[j] - t[j];
        float ad = fabsf(d);
        l1_acc += (ad < 1.0f) ? 0.5f * d * d : ad - 0.5f;
    }

    // quaternions -> rotation matrices
    float px = p[6], py = p[7], pz = p[8], pw = p[9];
    float gx = t[6], gy = t[7], gz = t[8], gw = t[9];
    float pin = rsqrtf(px*px + py*py + pz*pz + pw*pw);
    float gin = rsqrtf(gx*gx + gy*gy + gz*gz + gw*gw);
    px *= pin; py *= pin; pz *= pin; pw *= pin;
    gx *= gin; gy *= gin; gz *= gin; gw *= gin;

    float pr[9], gr[9];
    pr[0] = 1.0f - 2.0f*(py*py + pz*pz);
    pr[1] = 2.0f*(px*py + pz*pw);
    pr[2] = 2.0f*(px*pz - py*pw);
    pr[3] = 2.0f*(px*py - pz*pw);
    pr[4] = 1.0f - 2.0f*(px*px + pz*pz);
    pr[5] = 2.0f*(py*pz + px*pw);
    pr[6] = 2.0f*(px*pz + py*pw);
    pr[7] = 2.0f*(py*pz - px*pw);
    pr[8] = 1.0f - 2.0f*(px*px + py*py);

    gr[0] = 1.0f - 2.0f*(gy*gy + gz*gz);
    gr[1] = 2.0f*(gx*gy + gz*gw);
    gr[2] = 2.0f*(gx*gz - gy*gw);
    gr[3] = 2.0f*(gx*gy - gz*gw);
    gr[4] = 1.0f - 2.0f*(gx*gx + gz*gz);
    gr[5] = 2.0f*(gy*gz + gx*gw);
    gr[6] = 2.0f*(gx*gz + gy*gw);
    gr[7] = 2.0f*(gy*gz - gx*gw);
    gr[8] = 1.0f - 2.0f*(gx*gx + gy*gy);

    float dot = 0.0f;
    #pragma unroll
    for (int j = 0; j < 9; j++) dot += pr[j] * gr[j];
    float rot_align = fminf(fmaxf(dot * (1.0f / 3.0f), 0.0f), 1.0f);

    float prod = 1.0f;
    #pragma unroll
    for (int i = 0; i < 3; i++) {
        float pe = 0.5f * fabsf(pr[3*i]*p[3] + pr[3*i+1]*p[4] + pr[3*i+2]*p[5]);
        float ge = 0.5f * fabsf(gr[3*i]*t[3] + gr[3*i+1]*t[4] + gr[3*i+2]*t[5]);
        float cd  = fabsf(p[i] - t[i]);
        float num = fmaxf(2.0f * fminf(pe, ge) - cd, 0.0f);
        prod *= num / (pe + ge + EPSF);
    }
    ov_acc += fminf(fmaxf(prod * rot_align, 0.0f), 1.0f);
}

__global__ __launch_bounds__(THREADS) void hl_fused_kernel(
    const float* __restrict__ preds,
    const float* __restrict__ targets,
    float* __restrict__ out)
{
    const int tid  = threadIdx.x;
    const int pair = blockIdx.x * THREADS + tid;   // handles rows 2*pair, 2*pair+1

    float l1_sum = 0.0f;
    float ov     = 0.0f;

    if (pair < PAIRS) {
        // 80 bytes per thread, 16B aligned: 5 float4 per array
        const float4* __restrict__ p4 = reinterpret_cast<const float4*>(preds)   + (long)pair * 5;
        const float4* __restrict__ t4 = reinterpret_cast<const float4*>(targets) + (long)pair * 5;

        float4 pa0 = p4[0], pa1 = p4[1], pa2 = p4[2], pa3 = p4[3], pa4 = p4[4];
        float4 ta0 = t4[0], ta1 = t4[1], ta2 = t4[2], ta3 = t4[3], ta4 = t4[4];

        // row 0
        {
            float p[10] = {pa0.x, pa0.y, pa0.z, pa0.w, pa1.x, pa1.y, pa1.z, pa1.w, pa2.x, pa2.y};
            float t[10] = {ta0.x, ta0.y, ta0.z, ta0.w, ta1.x, ta1.y, ta1.z, ta1.w, ta2.x, ta2.y};
            row_math(p, t, l1_sum, ov);
        }
        // row 1
        {
            float p[10] = {pa2.z, pa2.w, pa3.x, pa3.y, pa3.z, pa3.w, pa4.x, pa4.y, pa4.z, pa4.w};
            float t[10] = {ta2.z, ta2.w, ta3.x, ta3.y, ta3.z, ta3.w, ta4.x, ta4.y, ta4.z, ta4.w};
            row_math(p, t, l1_sum, ov);
        }
    }

    // ---- block reduction (warp shuffle + smem) ----
    #pragma unroll
    for (int off = 16; off > 0; off >>= 1) {
        l1_sum += __shfl_down_sync(0xFFFFFFFFu, l1_sum, off);
        ov     += __shfl_down_sync(0xFFFFFFFFu, ov, off);
    }
    __shared__ float warp_l1[THREADS / 32];
    __shared__ float warp_ov[THREADS / 32];
    const int lane = tid & 31;
    const int wid  = tid >> 5;
    if (lane == 0) { warp_l1[wid] = l1_sum; warp_ov[wid] = ov; }
    __syncthreads();

    if (wid == 0) {
        float a = (lane < THREADS / 32) ? warp_l1[lane] : 0.0f;
        float b = (lane < THREADS / 32) ? warp_ov[lane] : 0.0f;
        #pragma unroll
        for (int off = 4; off > 0; off >>= 1) {
            a += __shfl_down_sync(0xFFFFFFFFu, a, off);
            b += __shfl_down_sync(0xFFFFFFFFu, b, off);
        }
        if (lane == 0) {
            atomicAdd(&g_acc[0], (double)a);
            atomicAdd(&g_acc[1], (double)b);
            __threadfence();
            unsigned int ticket = atomicAdd(&g_ticket, 1u);
            if (ticket == (unsigned int)(NBLOCKS - 1)) {
                double s0 = *((volatile double*)&g_acc[0]);
                double s1 = *((volatile double*)&g_acc[1]);
                double param_loss = s0 / ((double)NROWS * 10.0);
                double mean_ov    = s1 / (double)NROWS;
                out[0] = (float)(param_loss + 0.5 * (1.0 - mean_ov));
                // self-reset for next graph replay
                *((volatile double*)&g_acc[0]) = 0.0;
                *((volatile double*)&g_acc[1]) = 0.0;
                __threadfence();
                g_ticket = 0;
                __threadfence();
            }
        }
    }
}

extern "C" void kernel_launch(void* const* d_in, const int* in_sizes, int n_in,
                              void* d_out, int out_size) {
    const float* preds   = (const float*)d_in[0];
    const float* targets = (const float*)d_in[1];
    float* out = (float*)d_out;

    hl_fused_kernel<<<NBLOCKS, THREADS>>>(preds, targets, out);
}

// round 4
// speedup vs baseline: 1.2340x; 1.1892x over previous
#include <cuda_runtime.h>

// HybridLoss: smooth_l1(preds,targets) + 0.5*(1 - mean(box_overlap))
// preds, targets: [2000000, 10] float32 row-major. Output: 1 float scalar.
//
// Persistent grid-stride kernel (1 wave, 444 CTAs x 256 thr), 1 row/thread
// per iteration, software prefetch: next iteration's loads issue before the
// current iteration's math, keeping DRAM continuously busy.

#define NROWS 2000000
#define THREADS 256
#define NBLOCKS 444                                  // 148 SMs * 3 CTAs
#define TOTALT (NBLOCKS * THREADS)                   // 113,664
#define ITERS ((NROWS + TOTALT - 1) / TOTALT)        // 18
#define EPSF 1e-6f

__device__ double g_acc[2] = {0.0, 0.0};
__device__ unsigned int g_ticket = 0;

__device__ __forceinline__ void load_row(const float2* __restrict__ p2,
                                         const float2* __restrict__ t2,
                                         long row, float2* bp, float2* bt)
{
    const float2* rp = p2 + row * 5;   // 40B rows -> 5 float2, 8B aligned
    const float2* rt = t2 + row * 5;
    #pragma unroll
    for (int j = 0; j < 5; j++) { bp[j] = rp[j]; bt[j] = rt[j]; }
}

__device__ __forceinline__ void row_math(const float2* __restrict__ bp,
                                         const float2* __restrict__ bt,
                                         float& l1_acc, float& ov_acc)
{
    float p[10], t[10];
    #pragma unroll
    for (int j = 0; j < 5; j++) {
        p[2*j] = bp[j].x; p[2*j+1] = bp[j].y;
        t[2*j] = bt[j].x; t[2*j+1] = bt[j].y;
    }

    // smooth L1
    #pragma unroll
    for (int j = 0; j < 10; j++) {
        float d  = p[j] - t[j];
        float ad = fabsf(d);
        l1_acc += (ad < 1.0f) ? 0.5f * d * d : ad - 0.5f;
    }

    // normalized quaternions
    float px = p[6], py = p[7], pz = p[8], pw = p[9];
    float gx = t[6], gy = t[7], gz = t[8], gw = t[9];
    float pin = rsqrtf(px*px + py*py + pz*pz + pw*pw);
    float gin = rsqrtf(gx*gx + gy*gy + gz*gz + gw*gw);
    px *= pin; py *= pin; pz *= pin; pw *= pin;
    gx *= gin; gy *= gin; gz *= gin; gw *= gin;

    // rot_align via quaternion identity: trace(Rp^T Rg) = 4*(qp.qg)^2 - 1
    float qd = px*gx + py*gy + pz*gz + pw*gw;
    float rot_align = fminf(fmaxf((4.0f*qd*qd - 1.0f) * (1.0f/3.0f), 0.0f), 1.0f);

    // rotation matrices (needed for extents)
    float pr[9], gr[9];
    pr[0] = 1.0f - 2.0f*(py*py + pz*pz);
    pr[1] = 2.0f*(px*py + pz*pw);
    pr[2] = 2.0f*(px*pz - py*pw);
    pr[3] = 2.0f*(px*py - pz*pw);
    pr[4] = 1.0f - 2.0f*(px*px + pz*pz);
    pr[5] = 2.0f*(py*pz + px*pw);
    pr[6] = 2.0f*(px*pz + py*pw);
    pr[7] = 2.0f*(py*pz - px*pw);
    pr[8] = 1.0f - 2.0f*(px*px + py*py);

    gr[0] = 1.0f - 2.0f*(gy*gy + gz*gz);
    gr[1] = 2.0f*(gx*gy + gz*gw);
    gr[2] = 2.0f*(gx*gz - gy*gw);
    gr[3] = 2.0f*(gx*gy - gz*gw);
    gr[4] = 1.0f - 2.0f*(gx*gx + gz*gz);
    gr[5] = 2.0f*(gy*gz + gx*gw);
    gr[6] = 2.0f*(gx*gz + gy*gw);
    gr[7] = 2.0f*(gy*gz - gx*gw);
    gr[8] = 1.0f - 2.0f*(gx*gx + gy*gy);

    float prod = 1.0f;
    #pragma unroll
    for (int i = 0; i < 3; i++) {
        float pe = 0.5f * fabsf(pr[3*i]*p[3] + pr[3*i+1]*p[4] + pr[3*i+2]*p[5]);
        float ge = 0.5f * fabsf(gr[3*i]*t[3] + gr[3*i+1]*t[4] + gr[3*i+2]*t[5]);
        float cd  = fabsf(p[i] - t[i]);
        float num = fmaxf(2.0f * fminf(pe, ge) - cd, 0.0f);
        prod *= num / (pe + ge + EPSF);
    }
    ov_acc += fminf(fmaxf(prod * rot_align, 0.0f), 1.0f);
}

__global__ __launch_bounds__(THREADS, 3) void hl_fused_kernel(
    const float* __restrict__ preds,
    const float* __restrict__ targets,
    float* __restrict__ out)
{
    const int  tid  = threadIdx.x;
    const long row0 = (long)blockIdx.x * THREADS + tid;

    const float2* __restrict__ p2 = reinterpret_cast<const float2*>(preds);
    const float2* __restrict__ t2 = reinterpret_cast<const float2*>(targets);

    float l1_sum = 0.0f;
    float ov     = 0.0f;

    float2 cp[5], ct[5];
    if (row0 < NROWS) load_row(p2, t2, row0, cp, ct);

    #pragma unroll 1
    for (int it = 0; it < ITERS; it++) {
        const long row  = row0 + (long)it * TOTALT;
        const long nrow = row + TOTALT;

        float2 np[5], nt[5];
        if (it + 1 < ITERS && nrow < NROWS)
            load_row(p2, t2, nrow, np, nt);      // prefetch next iteration

        if (row < NROWS)
            row_math(cp, ct, l1_sum, ov);        // compute current (hides latency)

        #pragma unroll
        for (int j = 0; j < 5; j++) { cp[j] = np[j]; ct[j] = nt[j]; }
    }

    // ---- block reduction ----
    #pragma unroll
    for (int off = 16; off > 0; off >>= 1) {
        l1_sum += __shfl_down_sync(0xFFFFFFFFu, l1_sum, off);
        ov     += __shfl_down_sync(0xFFFFFFFFu, ov, off);
    }
    __shared__ float warp_l1[THREADS / 32];
    __shared__ float warp_ov[THREADS / 32];
    const int lane = tid & 31;
    const int wid  = tid >> 5;
    if (lane == 0) { warp_l1[wid] = l1_sum; warp_ov[wid] = ov; }
    __syncthreads();

    if (wid == 0) {
        float a = (lane < THREADS / 32) ? warp_l1[lane] : 0.0f;
        float b = (lane < THREADS / 32) ? warp_ov[lane] : 0.0f;
        #pragma unroll
        for (int off = 4; off > 0; off >>= 1) {
            a += __shfl_down_sync(0xFFFFFFFFu, a, off);
            b += __shfl_down_sync(0xFFFFFFFFu, b, off);
        }
        if (lane == 0) {
            atomicAdd(&g_acc[0], (double)a);
            atomicAdd(&g_acc[1], (double)b);
            __threadfence();
            unsigned int ticket = atomicAdd(&g_ticket, 1u);
            if (ticket == (unsigned int)(NBLOCKS - 1)) {
                double s0 = *((volatile double*)&g_acc[0]);
                double s1 = *((volatile double*)&g_acc[1]);
                double param_loss = s0 / ((double)NROWS * 10.0);
                double mean_ov    = s1 / (double)NROWS;
                out[0] = (float)(param_loss + 0.5 * (1.0 - mean_ov));
                *((volatile double*)&g_acc[0]) = 0.0;
                *((volatile double*)&g_acc[1]) = 0.0;
                __threadfence();
                g_ticket = 0;
                __threadfence();
            }
        }
    }
}

extern "C" void kernel_launch(void* const* d_in, const int* in_sizes, int n_in,
                              void* d_out, int out_size) {
    const float* preds   = (const float*)d_in[0];
    const float* targets = (const float*)d_in[1];
    float* out = (float*)d_out;

    hl_fused_kernel<<<NBLOCKS, THREADS>>>(preds, targets, out);
}

// round 5
// speedup vs baseline: 1.4507x; 1.1756x over previous
#include <cuda_runtime.h>

// HybridLoss: smooth_l1(preds,targets) + 0.5*(1 - mean(box_overlap))
// preds, targets: [2000000, 10] float32 row-major. Output: 1 float scalar.
//
// Persistent 1-wave kernel (592 CTAs x 256 thr, 4 CTA/SM), software prefetch.
// Math uses unnormalized-quaternion identities: R = M/|q|^2, so no rsqrt/
// normalization; extents scale by 0.5/|q|^2; trace identity for rot_align.
// Row-wise matrix evaluation keeps register pressure under the 64-reg cap.

#define NROWS 2000000
#define THREADS 256
#define NBLOCKS 592                                  // 148 SMs * 4 CTAs
#define TOTALT (NBLOCKS * THREADS)                   // 151,552
#define ITERS ((NROWS + TOTALT - 1) / TOTALT)        // 14
#define EPSF 1e-6f

__device__ double g_acc[2] = {0.0, 0.0};
__device__ unsigned int g_ticket = 0;

__device__ __forceinline__ void load_row(const float2* __restrict__ p2,
                                         const float2* __restrict__ t2,
                                         long row, float2* bp, float2* bt)
{
    const float2* rp = p2 + row * 5;   // 40B rows -> 5 float2, 8B aligned
    const float2* rt = t2 + row * 5;
    #pragma unroll
    for (int j = 0; j < 5; j++) { bp[j] = rp[j]; bt[j] = rt[j]; }
}

__device__ __forceinline__ void row_math(const float2* __restrict__ bp,
                                         const float2* __restrict__ bt,
                                         float& l1_acc, float& ov_acc)
{
    float p[10], t[10];
    #pragma unroll
    for (int j = 0; j < 5; j++) {
        p[2*j] = bp[j].x; p[2*j+1] = bp[j].y;
        t[2*j] = bt[j].x; t[2*j+1] = bt[j].y;
    }

    // ---- smooth L1 ----
    #pragma unroll
    for (int j = 0; j < 10; j++) {
        float d  = p[j] - t[j];
        float ad = fabsf(d);
        l1_acc += (ad < 1.0f) ? 0.5f * d * d : ad - 0.5f;
    }

    // ---- raw quaternions (no normalization) ----
    const float px = p[6], py = p[7], pz = p[8], pw = p[9];
    const float gx = t[6], gy = t[7], gz = t[8], gw = t[9];
    const float Ap = px*px + py*py + pz*pz + pw*pw;
    const float Ag = gx*gx + gy*gy + gz*gz + gw*gw;
    const float rp = 1.0f / Ap;
    const float rg = 1.0f / Ag;

    // rot_align: trace(Rp^T Rg)/3 = (4*(qp.qg)^2/(Ap*Ag) - 1)/3
    const float dq  = px*gx + py*gy + pz*gz + pw*gw;
    const float qd2 = dq * dq * rp * rg;
    const float rot_align = fminf(fmaxf((4.0f*qd2 - 1.0f) * (1.0f/3.0f), 0.0f), 1.0f);

    // ---- extents row-by-row: pe_i = (0.5/Ap)*|M_i . d| ----
    const float sp = 0.5f * rp;
    const float sg = 0.5f * rg;
    const float dpx = p[3], dpy = p[4], dpz = p[5];
    const float dgx = t[3], dgy = t[4], dgz = t[5];

    float num = 1.0f, den = 1.0f;

    // row 0: (A-2(y^2+z^2), 2(xy+zw), 2(xz-yw))
    {
        float mp = (Ap - 2.0f*(py*py + pz*pz))*dpx + 2.0f*(px*py + pz*pw)*dpy + 2.0f*(px*pz - py*pw)*dpz;
        float mg = (Ag - 2.0f*(gy*gy + gz*gz))*dgx + 2.0f*(gx*gy + gz*gw)*dgy + 2.0f*(gx*gz - gy*gw)*dgz;
        float pe = sp * fabsf(mp);
        float ge = sg * fabsf(mg);
        float cd = fabsf(p[0] - t[0]);
        num *= fmaxf(2.0f * fminf(pe, ge) - cd, 0.0f);
        den *= pe + ge + EPSF;
    }
    // row 1: (2(xy-zw), A-2(x^2+z^2), 2(yz+xw))
    {
        float mp = 2.0f*(px*py - pz*pw)*dpx + (Ap - 2.0f*(px*px + pz*pz))*dpy + 2.0f*(py*pz + px*pw)*dpz;
        float mg = 2.0f*(gx*gy - gz*gw)*dgx + (Ag - 2.0f*(gx*gx + gz*gz))*dgy + 2.0f*(gy*gz + gx*gw)*dgz;
        float pe = sp * fabsf(mp);
        float ge = sg * fabsf(mg);
        float cd = fabsf(p[1] - t[1]);
        num *= fmaxf(2.0f * fminf(pe, ge) - cd, 0.0f);
        den *= pe + ge + EPSF;
    }
    // row 2: (2(xz+yw), 2(yz-xw), A-2(x^2+y^2))
    {
        float mp = 2.0f*(px*pz + py*pw)*dpx + 2.0f*(py*pz - px*pw)*dpy + (Ap - 2.0f*(px*px + py*py))*dpz;
        float mg = 2.0f*(gx*gz + gy*gw)*dgx + 2.0f*(gy*gz - gx*gw)*dgy + (Ag - 2.0f*(gx*gx + gy*gy))*dgz;
        float pe = sp * fabsf(mp);
        float ge = sg * fabsf(mg);
        float cd = fabsf(p[2] - t[2]);
        num *= fmaxf(2.0f * fminf(pe, ge) - cd, 0.0f);
        den *= pe + ge + EPSF;
    }

    float prod = (num / den) * rot_align;
    ov_acc += fminf(fmaxf(prod, 0.0f), 1.0f);
}

__global__ __launch_bounds__(THREADS, 4) void hl_fused_kernel(
    const float* __restrict__ preds,
    const float* __restrict__ targets,
    float* __restrict__ out)
{
    const int  tid  = threadIdx.x;
    const long row0 = (long)blockIdx.x * THREADS + tid;

    const float2* __restrict__ p2 = reinterpret_cast<const float2*>(preds);
    const float2* __restrict__ t2 = reinterpret_cast<const float2*>(targets);

    float l1_sum = 0.0f;
    float ov     = 0.0f;

    float2 cp[5], ct[5];
    if (row0 < NROWS) load_row(p2, t2, row0, cp, ct);

    #pragma unroll 1
    for (int it = 0; it < ITERS; it++) {
        const long row  = row0 + (long)it * TOTALT;
        const long nrow = row + TOTALT;

        float2 np[5], nt[5];
        if (it + 1 < ITERS && nrow < NROWS)
            load_row(p2, t2, nrow, np, nt);      // prefetch next iteration

        if (row < NROWS)
            row_math(cp, ct, l1_sum, ov);        // compute current (hides latency)

        #pragma unroll
        for (int j = 0; j < 5; j++) { cp[j] = np[j]; ct[j] = nt[j]; }
    }

    // ---- block reduction ----
    #pragma unroll
    for (int off = 16; off > 0; off >>= 1) {
        l1_sum += __shfl_down_sync(0xFFFFFFFFu, l1_sum, off);
        ov     += __shfl_down_sync(0xFFFFFFFFu, ov, off);
    }
    __shared__ float warp_l1[THREADS / 32];
    __shared__ float warp_ov[THREADS / 32];
    const int lane = tid & 31;
    const int wid  = tid >> 5;
    if (lane == 0) { warp_l1[wid] = l1_sum; warp_ov[wid] = ov; }
    __syncthreads();

    if (wid == 0) {
        float a = (lane < THREADS / 32) ? warp_l1[lane] : 0.0f;
        float b = (lane < THREADS / 32) ? warp_ov[lane] : 0.0f;
        #pragma unroll
        for (int off = 4; off > 0; off >>= 1) {
            a += __shfl_down_sync(0xFFFFFFFFu, a, off);
            b += __shfl_down_sync(0xFFFFFFFFu, b, off);
        }
        if (lane == 0) {
            atomicAdd(&g_acc[0], (double)a);
            atomicAdd(&g_acc[1], (double)b);
            __threadfence();
            unsigned int ticket = atomicAdd(&g_ticket, 1u);
            if (ticket == (unsigned int)(NBLOCKS - 1)) {
                double s0 = *((volatile double*)&g_acc[0]);
                double s1 = *((volatile double*)&g_acc[1]);
                double param_loss = s0 / ((double)NROWS * 10.0);
                double mean_ov    = s1 / (double)NROWS;
                out[0] = (float)(param_loss + 0.5 * (1.0 - mean_ov));
                *((volatile double*)&g_acc[0]) = 0.0;
                *((volatile double*)&g_acc[1]) = 0.0;
                __threadfence();
                g_ticket = 0;
                __threadfence();
            }
        }
    }
}

extern "C" void kernel_launch(void* const* d_in, const int* in_sizes, int n_in,
                              void* d_out, int out_size) {
    const float* preds   = (const float*)d_in[0];
    const float* targets = (const float*)d_in[1];
    float* out = (float*)d_out;

    hl_fused_kernel<<<NBLOCKS, THREADS>>>(preds, targets, out);
}

// round 6
// speedup vs baseline: 1.5005x; 1.0343x over previous
#include <cuda_runtime.h>

// HybridLoss: smooth_l1(preds,targets) + 0.5*(1 - mean(box_overlap))
// preds, targets: [2000000, 10] float32 row-major. Output: 1 float scalar.
//
// Persistent 1-wave kernel (592 CTAs x 256 thr, 4 CTA/SM), software prefetch.
// Unnormalized-quaternion identities (no rsqrt); single fast reciprocal for
// both quat norms; select-free Huber; provably redundant clamps removed.

#define NROWS 2000000
#define THREADS 256
#define NBLOCKS 592                                  // 148 SMs * 4 CTAs
#define TOTALT (NBLOCKS * THREADS)                   // 151,552
#define ITERS ((NROWS + TOTALT - 1) / TOTALT)        // 14
#define EPSF 1e-6f

__device__ double g_acc[2] = {0.0, 0.0};
__device__ unsigned int g_ticket = 0;

__device__ __forceinline__ void load_row(const float2* __restrict__ p2,
                                         const float2* __restrict__ t2,
                                         int row, float2* bp, float2* bt)
{
    const float2* rp = p2 + (size_t)row * 5;   // 40B rows -> 5 float2
    const float2* rt = t2 + (size_t)row * 5;
    #pragma unroll
    for (int j = 0; j < 5; j++) { bp[j] = rp[j]; bt[j] = rt[j]; }
}

__device__ __forceinline__ void row_math(const float2* __restrict__ bp,
                                         const float2* __restrict__ bt,
                                         float& l1_acc, float& ov_acc)
{
    float p[10], t[10];
    #pragma unroll
    for (int j = 0; j < 5; j++) {
        p[2*j] = bp[j].x; p[2*j+1] = bp[j].y;
        t[2*j] = bt[j].x; t[2*j+1] = bt[j].y;
    }

    // ---- smooth L1, select-free: m=min(|d|,1); term = m*(|d| - 0.5m) ----
    #pragma unroll
    for (int j = 0; j < 10; j++) {
        float d  = p[j] - t[j];
        float ad = fabsf(d);
        float m  = fminf(ad, 1.0f);
        l1_acc = fmaf(m, fmaf(-0.5f, m, ad), l1_acc);
    }

    // ---- raw quaternions (no normalization) ----
    const float px = p[6], py = p[7], pz = p[8], pw = p[9];
    const float gx = t[6], gy = t[7], gz = t[8], gw = t[9];
    const float Ap = px*px + py*py + pz*pz + pw*pw;
    const float Ag = gx*gx + gy*gy + gz*gz + gw*gw;
    const float rpg = __fdividef(1.0f, Ap * Ag);   // 1/(Ap*Ag), fast path
    const float rp  = Ag * rpg;                    // 1/Ap
    const float rg  = Ap * rpg;                    // 1/Ag

    // rot_align = max((4*dq^2/(Ap*Ag) - 1)/3, 0); upper bound 1 is automatic
    const float dq  = px*gx + py*gy + pz*gz + pw*gw;
    const float rot_align = fmaxf(fmaf(4.0f * dq * dq, rpg, -1.0f) * (1.0f/3.0f), 0.0f);

    // ---- extents row-by-row: pe_i = (0.5/Ap)*|M_i . d| ----
    const float sp = 0.5f * rp;
    const float sg = 0.5f * rg;
    const float dpx = p[3], dpy = p[4], dpz = p[5];
    const float dgx = t[3], dgy = t[4], dgz = t[5];

    float num = 1.0f, den = 1.0f;

    // row 0
    {
        float mp = (Ap - 2.0f*(py*py + pz*pz))*dpx + 2.0f*(px*py + pz*pw)*dpy + 2.0f*(px*pz - py*pw)*dpz;
        float mg = (Ag - 2.0f*(gy*gy + gz*gz))*dgx + 2.0f*(gx*gy + gz*gw)*dgy + 2.0f*(gx*gz - gy*gw)*dgz;
        float pe = sp * fabsf(mp);
        float ge = sg * fabsf(mg);
        float cd = fabsf(p[0] - t[0]);
        num *= fmaxf(2.0f * fminf(pe, ge) - cd, 0.0f);
        den *= pe + ge + EPSF;
    }
    // row 1
    {
        float mp = 2.0f*(px*py - pz*pw)*dpx + (Ap - 2.0f*(px*px + pz*pz))*dpy + 2.0f*(py*pz + px*pw)*dpz;
        float mg = 2.0f*(gx*gy - gz*gw)*dgx + (Ag - 2.0f*(gx*gx + gz*gz))*dgy + 2.0f*(gy*gz + gx*gw)*dgz;
        float pe = sp * fabsf(mp);
        float ge = sg * fabsf(mg);
        float cd = fabsf(p[1] - t[1]);
        num *= fmaxf(2.0f * fminf(pe, ge) - cd, 0.0f);
        den *= pe + ge + EPSF;
    }
    // row 2
    {
        float mp = 2.0f*(px*pz + py*pw)*dpx + 2.0f*(py*pz - px*pw)*dpy + (Ap - 2.0f*(px*px + py*py))*dpz;
        float mg = 2.0f*(gx*gz + gy*gw)*dgx + 2.0f*(gy*gz - gx*gw)*dgy + (Ag - 2.0f*(gx*gx + gy*gy))*dgz;
        float pe = sp * fabsf(mp);
        float ge = sg * fabsf(mg);
        float cd = fabsf(p[2] - t[2]);
        num *= fmaxf(2.0f * fminf(pe, ge) - cd, 0.0f);
        den *= pe + ge + EPSF;
    }

    // num/den in [0,1), rot_align in [0,1] -> no clamp needed on the product
    ov_acc += __fdividef(num * rot_align, den);
}

__global__ __launch_bounds__(THREADS, 4) void hl_fused_kernel(
    const float* __restrict__ preds,
    const float* __restrict__ targets,
    float* __restrict__ out)
{
    const int tid  = threadIdx.x;
    const int row0 = blockIdx.x * THREADS + tid;

    const float2* __restrict__ p2 = reinterpret_cast<const float2*>(preds);
    const float2* __restrict__ t2 = reinterpret_cast<const float2*>(targets);

    float l1_sum = 0.0f;
    float ov     = 0.0f;

    float2 cp[5], ct[5];
    if (row0 < NROWS) load_row(p2, t2, row0, cp, ct);

    #pragma unroll 1
    for (int it = 0; it < ITERS; it++) {
        const int row  = row0 + it * TOTALT;
        const int nrow = row + TOTALT;

        float2 np[5], nt[5];
        if (it + 1 < ITERS && nrow < NROWS)
            load_row(p2, t2, nrow, np, nt);      // prefetch next iteration

        if (row < NROWS)
            row_math(cp, ct, l1_sum, ov);        // compute current (hides latency)

        #pragma unroll
        for (int j = 0; j < 5; j++) { cp[j] = np[j]; ct[j] = nt[j]; }
    }

    // ---- block reduction ----
    #pragma unroll
    for (int off = 16; off > 0; off >>= 1) {
        l1_sum += __shfl_down_sync(0xFFFFFFFFu, l1_sum, off);
        ov     += __shfl_down_sync(0xFFFFFFFFu, ov, off);
    }
    __shared__ float warp_l1[THREADS / 32];
    __shared__ float warp_ov[THREADS / 32];
    const int lane = tid & 31;
    const int wid  = tid >> 5;
    if (lane == 0) { warp_l1[wid] = l1_sum; warp_ov[wid] = ov; }
    __syncthreads();

    if (wid == 0) {
        float a = (lane < THREADS / 32) ? warp_l1[lane] : 0.0f;
        float b = (lane < THREADS / 32) ? warp_ov[lane] : 0.0f;
        #pragma unroll
        for (int off = 4; off > 0; off >>= 1) {
            a += __shfl_down_sync(0xFFFFFFFFu, a, off);
            b += __shfl_down_sync(0xFFFFFFFFu, b, off);
        }
        if (lane == 0) {
            atomicAdd(&g_acc[0], (double)a);
            atomicAdd(&g_acc[1], (double)b);
            __threadfence();
            unsigned int ticket = atomicAdd(&g_ticket, 1u);
            if (ticket == (unsigned int)(NBLOCKS - 1)) {
                double s0 = *((volatile double*)&g_acc[0]);
                double s1 = *((volatile double*)&g_acc[1]);
                double param_loss = s0 / ((double)NROWS * 10.0);
                double mean_ov    = s1 / (double)NROWS;
                out[0] = (float)(param_loss + 0.5 * (1.0 - mean_ov));
                *((volatile double*)&g_acc[0]) = 0.0;
                *((volatile double*)&g_acc[1]) = 0.0;
                __threadfence();
                g_ticket = 0;
                __threadfence();
            }
        }
    }
}

extern "C" void kernel_launch(void* const* d_in, const int* in_sizes, int n_in,
                              void* d_out, int out_size) {
    const float* preds   = (const float*)d_in[0];
    const float* targets = (const float*)d_in[1];
    float* out = (float*)d_out;

    hl_fused_kernel<<<NBLOCKS, THREADS>>>(preds, targets, out);
}